// round 1
// baseline (speedup 1.0000x reference)
#include <cuda_runtime.h>
#include <math.h>

// Problem constants
#define Bb 4
#define Ss 20
#define IMm 64
#define Dd 8
#define Hh 4
#define Ee 4
#define NLl 4
#define NPOS (Bb*Ss*IMm*IMm)      // 327680 spatial positions
#define NELEM (NPOS*Dd)           // 2621440 floats

// Scratch (no allocations allowed)
__device__ float g_xt[NELEM];
__device__ float g_bufA[NELEM];
__device__ float g_bufB[NELEM];
__device__ float g_logits[Bb];

// ---------------------------------------------------------------------------
// Embed: xt[b,s,h,w,d] = relu(x*conv_w[d]) + pos_s[s,d] + pos_h[d,h] + pos_w[d,w]
// Also zeroes g_logits (deterministic per launch).
// ---------------------------------------------------------------------------
__global__ void embed_kernel(const float* __restrict__ x,
                             const float* __restrict__ conv_w,
                             const float* __restrict__ pos_s,
                             const float* __restrict__ pos_h,
                             const float* __restrict__ pos_w)
{
    int idx = blockIdx.x * blockDim.x + threadIdx.x;
    if (idx < Bb) g_logits[idx] = 0.0f;
    if (idx >= NPOS) return;
    int w = idx & 63;
    int t = idx >> 6;
    int h = t & 63;
    t >>= 6;
    int s = t % Ss;
    float xv = x[idx];
    float vals[8];
#pragma unroll
    for (int d = 0; d < 8; d++) {
        float v = fmaxf(xv * conv_w[d], 0.0f);
        v += pos_s[s * 8 + d] + pos_h[d * 64 + h] + pos_w[d * 64 + w];
        vals[d] = v;
    }
    float4* o = (float4*)(g_xt + (long)idx * 8);
    o[0] = make_float4(vals[0], vals[1], vals[2], vals[3]);
    o[1] = make_float4(vals[4], vals[5], vals[6], vals[7]);
}

// ---------------------------------------------------------------------------
// Axial attention. One thread = one row i of one sequence.
// blockDim = (L, NS). Sequence -> base row offset:
//   outer = seq / inner_count; rem = seq % inner_count;
//   base = outer*outer_mult + rem;  row r at (base + r*stride)*8 floats.
// ---------------------------------------------------------------------------
template<int L, int NS>
__global__ void __launch_bounds__(L*NS)
axial_attn(const float* __restrict__ zin, float* __restrict__ zout,
           const float* __restrict__ Wq, const float* __restrict__ Wkv,
           const float* __restrict__ Wo, const float* __restrict__ bo,
           int inner_count, int outer_mult, int stride, int accum)
{
    __shared__ float sWq[128];
    __shared__ float sWkv[256];
    __shared__ float sWo[128];
    __shared__ float sbo[8];
    __shared__ float4 sK[NS][4][L];   // head-major: conflict-free f4 stores, broadcast reads
    __shared__ float4 sV[NS][4][L];

    const int i   = threadIdx.x;        // row within sequence
    const int sl  = threadIdx.y;        // sequence slot within block
    const int tid = sl * L + i;
    const int nth = L * NS;

    for (int t = tid; t < 128; t += nth) sWq[t]  = Wq[t];
    for (int t = tid; t < 256; t += nth) sWkv[t] = Wkv[t];
    for (int t = tid; t < 128; t += nth) sWo[t]  = Wo[t];
    if (tid < 8) sbo[tid] = bo[tid];

    const int seq   = blockIdx.x * NS + sl;
    const int outer = seq / inner_count;
    const int rem   = seq - outer * inner_count;
    const long base = (long)outer * outer_mult + rem;

    // load my row (8 floats)
    const float* zr = zin + (base + (long)i * stride) * 8;
    float4 a0 = *(const float4*)zr;
    float4 a1 = *(const float4*)(zr + 4);
    float row[8] = {a0.x, a0.y, a0.z, a0.w, a1.x, a1.y, a1.z, a1.w};

    __syncthreads();   // weights ready

    // q projection (16)
    float q[16];
#pragma unroll
    for (int c = 0; c < 16; c++) {
        float s = 0.0f;
#pragma unroll
        for (int d = 0; d < 8; d++) s = fmaf(row[d], sWq[d * 16 + c], s);
        q[c] = s;
    }
    // k,v projections -> shared
#pragma unroll
    for (int h = 0; h < 4; h++) {
        float4 kk, vv;
        float* kp = (float*)&kk;
        float* vp = (float*)&vv;
#pragma unroll
        for (int e = 0; e < 4; e++) {
            float sk = 0.0f, sv = 0.0f;
#pragma unroll
            for (int d = 0; d < 8; d++) {
                sk = fmaf(row[d], sWkv[d * 32 + h * 4 + e], sk);
                sv = fmaf(row[d], sWkv[d * 32 + 16 + h * 4 + e], sv);
            }
            kp[e] = sk; vp[e] = sv;
        }
        sK[sl][h][i] = kk;
        sV[sl][h][i] = vv;
    }
    __syncthreads();

    // attention per head
    float oacc[16];
#pragma unroll
    for (int h = 0; h < 4; h++) {
        const float qx = q[h*4+0], qy = q[h*4+1], qz = q[h*4+2], qw = q[h*4+3];
        float p[L];
        float m = -1e30f;
#pragma unroll
        for (int j = 0; j < L; j++) {
            float4 kj = sK[sl][h][j];
            float d = qx*kj.x + qy*kj.y + qz*kj.z + qw*kj.w;
            d *= 0.5f;   // E^-0.5
            p[j] = d;
            m = fmaxf(m, d);
        }
        float ssum = 0.0f;
        float ox = 0.f, oy = 0.f, oz = 0.f, ow = 0.f;
#pragma unroll
        for (int j = 0; j < L; j++) {
            float e = __expf(p[j] - m);
            ssum += e;
            float4 vj = sV[sl][h][j];
            ox = fmaf(e, vj.x, ox);
            oy = fmaf(e, vj.y, oy);
            oz = fmaf(e, vj.z, oz);
            ow = fmaf(e, vj.w, ow);
        }
        float inv = 1.0f / ssum;
        oacc[h*4+0] = ox * inv;
        oacc[h*4+1] = oy * inv;
        oacc[h*4+2] = oz * inv;
        oacc[h*4+3] = ow * inv;
    }

    // output projection (16 -> 8) + bias
    float outv[8];
#pragma unroll
    for (int d = 0; d < 8; d++) {
        float s = sbo[d];
#pragma unroll
        for (int c = 0; c < 16; c++) s = fmaf(oacc[c], sWo[c * 8 + d], s);
        outv[d] = s;
    }

    float* zo = zout + (base + (long)i * stride) * 8;
    if (accum) {
        float4 o0 = *(float4*)zo;
        float4 o1 = *(float4*)(zo + 4);
        outv[0] += o0.x; outv[1] += o0.y; outv[2] += o0.z; outv[3] += o0.w;
        outv[4] += o1.x; outv[5] += o1.y; outv[6] += o1.z; outv[7] += o1.w;
    }
    ((float4*)zo)[0] = make_float4(outv[0], outv[1], outv[2], outv[3]);
    ((float4*)zo)[1] = make_float4(outv[4], outv[5], outv[6], outv[7]);
}

// ---------------------------------------------------------------------------
// Epilogue reduce: m[b,h,w,d] = max_s(z+xt); logits[b] += m * Wc[d*4096+h*64+w]
// ---------------------------------------------------------------------------
__global__ void reduce_kernel(const float* __restrict__ zfin,
                              const float* __restrict__ Wc)
{
    const int b = blockIdx.y;
    const int t = blockIdx.x * blockDim.x + threadIdx.x;  // [0, 64*64*8)
    const int d  = t & 7;
    const int hw = t >> 3;             // h*64 + w
    long base = (long)b * Ss * 32768 + (long)hw * 8 + d;
    float m = -1e30f;
#pragma unroll
    for (int s = 0; s < Ss; s++) {
        long o = base + (long)s * 32768;
        m = fmaxf(m, zfin[o] + g_xt[o]);
    }
    float val = m * Wc[d * 4096 + hw];

    __shared__ float red[256];
    red[threadIdx.x] = val;
    __syncthreads();
    for (int off = 128; off > 0; off >>= 1) {
        if (threadIdx.x < off) red[threadIdx.x] += red[threadIdx.x + off];
        __syncthreads();
    }
    if (threadIdx.x == 0) atomicAdd(&g_logits[b], red[0]);
}

__global__ void final_kernel(const float* __restrict__ bc, float* __restrict__ out)
{
    int b = threadIdx.x;
    if (b < Bb) {
        float lg = g_logits[b] + bc[0];
        out[b] = 1.0f / (1.0f + __expf(-lg));
    }
}

// ---------------------------------------------------------------------------
extern "C" void kernel_launch(void* const* d_in, const int* in_sizes, int n_in,
                              void* d_out, int out_size)
{
    const float* x      = (const float*)d_in[0];
    const float* conv_w = (const float*)d_in[1];
    const float* pos_s  = (const float*)d_in[2];
    const float* pos_h  = (const float*)d_in[3];
    const float* pos_w  = (const float*)d_in[4];
    const float* Wq     = (const float*)d_in[5];
    const float* Wkv    = (const float*)d_in[6];
    const float* Wo     = (const float*)d_in[7];
    const float* bo     = (const float*)d_in[8];
    const float* Wc     = (const float*)d_in[9];
    const float* bc     = (const float*)d_in[10];
    float* out = (float*)d_out;

    float *pXt = nullptr, *pA = nullptr, *pB = nullptr;
    cudaGetSymbolAddress((void**)&pXt, g_xt);
    cudaGetSymbolAddress((void**)&pA,  g_bufA);
    cudaGetSymbolAddress((void**)&pB,  g_bufB);

    embed_kernel<<<(NPOS + 255) / 256, 256>>>(x, conv_w, pos_s, pos_h, pos_w);

    float* cur = pXt;
    for (int l = 0; l < NLl; l++) {
        float* nxt = (l & 1) ? pB : pA;      // l0: xt->A, l1: A->B, l2: B->A, l3: A->B
        if (l >= 1) nxt = ((l & 1) == 1) ? pB : pA;
        // weight offsets for (l, axis)
        const float* wq0 = Wq  + (l * 3 + 0) * 128;
        const float* wk0 = Wkv + (l * 3 + 0) * 256;
        const float* wo0 = Wo  + (l * 3 + 0) * 128;
        const float* bo0 = bo  + (l * 3 + 0) * 8;

        // axis 1 (S, L=20): write
        {
            dim3 blk(20, 8);
            axial_attn<20, 8><<<Bb * IMm * IMm / 8, blk>>>(
                cur, nxt, wq0, wk0, wo0, bo0,
                IMm * IMm, Ss * IMm * IMm, IMm * IMm, 0);
        }
        // axis 2 (H, L=64): accumulate
        {
            dim3 blk(64, 2);
            axial_attn<64, 2><<<Bb * Ss * IMm / 2, blk>>>(
                cur, nxt, wq0 + 128, wk0 + 256, wo0 + 128, bo0 + 8,
                IMm, IMm * IMm, IMm, 1);
        }
        // axis 3 (W, L=64): accumulate
        {
            dim3 blk(64, 2);
            axial_attn<64, 2><<<Bb * Ss * IMm / 2, blk>>>(
                cur, nxt, wq0 + 256, wk0 + 512, wo0 + 256, bo0 + 16,
                1, IMm, 1, 1);
        }
        cur = nxt;
    }

    {
        dim3 grid(IMm * IMm * Dd / 256, Bb);
        reduce_kernel<<<grid, 256>>>(cur, Wc);
    }
    final_kernel<<<1, 32>>>(bc, out);
}